// round 15
// baseline (speedup 1.0000x reference)
#include <cuda_runtime.h>
#include <cuda_bf16.h>
#include <cuda_fp16.h>
#include <mma.h>
#include <math.h>

using namespace nvcuda;

#define NN 100000
#define EE 1600000
#define NF 133
#define HD 128
#define NROWS 100096           // NN rounded up to 128
#define LDA 192                // g_ap row stride in elems (Kpad_max = 192)

typedef unsigned long long ull;
typedef unsigned int u32;

// ---------------- device scratch (static, no runtime alloc) ----------------
__device__ __half g_h0[(size_t)NROWS * HD];          // GEMM output ping
__device__ __half g_h1[(size_t)NROWS * HD];          // GEMM output pong
__device__ __half g_ap[(size_t)NROWS * LDA];         // A (fp16 activations / input)
__device__ __half g_bp[128 * 192 + 3 * 128 * 128];   // B regions: L0 | L1 | L2 | L3
__device__ float g_dinv[NN];
__device__ int   g_cnt[NN];
__device__ int   g_rowptr[NN];
__device__ int   g_fill[NN];
__device__ int   g_col[EE];
__device__ float g_wgt[EE];
__device__ int   g_bsum[256];
__device__ int   g_is64;

#define B_OFF_L0 0
#define B_OFF_L1 24576
#define B_OFF_L2 40960
#define B_OFF_L3 57344

// ---------------- cp.async helpers ----------------
__device__ __forceinline__ u32 smem_u32(const void* p) {
    u32 a;
    asm("{ .reg .u64 t; cvta.to.shared.u64 t, %1; cvt.u32.u64 %0, t; }" : "=r"(a) : "l"(p));
    return a;
}
__device__ __forceinline__ void cp16(u32 dst, const void* src) {
    asm volatile("cp.async.cg.shared.global [%0], [%1], 16;" :: "r"(dst), "l"(src));
}
__device__ __forceinline__ void cp_commit() {
    asm volatile("cp.async.commit_group;");
}
template <int N>
__device__ __forceinline__ void cp_wait() {
    asm volatile("cp.async.wait_group %0;" :: "n"(N));
}

// ---------------- probe + zero counters (merged) ----------------
__global__ void k_probe_zero(const int* __restrict__ ei, int n) {
    int i = blockIdx.x * blockDim.x + threadIdx.x;
    if (blockIdx.x == 0) {
        __shared__ int nz;
        if (threadIdx.x == 0) nz = 0;
        __syncthreads();
        int v = ei[threadIdx.x * 2 + 1];
        if (v != 0) atomicAdd(&nz, 1);
        __syncthreads();
        if (threadIdx.x == 0) g_is64 = (nz == 0) ? 1 : 0;
    }
    if (i < n) g_cnt[i] = 0;
}

__device__ __forceinline__ int edge_val(const void* ei, long long idx) {
    if (g_is64) return (int)((const long long*)ei)[idx];
    return ((const int*)ei)[idx];
}

// ---------------- CSR build ----------------
__global__ void k_count(const void* __restrict__ ei, int e) {
    int i = blockIdx.x * blockDim.x + threadIdx.x;
    if (i >= e) return;
    int d = edge_val(ei, (long long)e + i);
    atomicAdd(&g_cnt[d], 1);
}

__global__ void k_scan1(int n) {
    __shared__ int s[1024];
    int t = threadIdx.x;
    int i = blockIdx.x * 1024 + t;
    int v = (i < n) ? g_cnt[i] : 0;
    s[t] = v;
    __syncthreads();
    #pragma unroll
    for (int off = 1; off < 1024; off <<= 1) {
        int x = (t >= off) ? s[t - off] : 0;
        __syncthreads();
        s[t] += x;
        __syncthreads();
    }
    if (i < n) g_rowptr[i] = s[t] - v;
    if (t == 1023) g_bsum[blockIdx.x] = s[1023];
}

__global__ void k_scan2(int nb) {
    if (threadIdx.x == 0) {
        int run = 0;
        for (int b = 0; b < nb; b++) { int t = g_bsum[b]; g_bsum[b] = run; run += t; }
    }
}

__global__ void k_scan3(int n) {
    int i = blockIdx.x * blockDim.x + threadIdx.x;
    if (i >= n) return;
    int r = g_rowptr[i] + g_bsum[i >> 10];
    g_rowptr[i] = r;
    g_fill[i]   = r;
    g_dinv[i]   = rsqrtf((float)g_cnt[i] + 1.0f);
}

__global__ void k_fill(const void* __restrict__ ei, int e) {
    int i = blockIdx.x * blockDim.x + threadIdx.x;
    if (i >= e) return;
    int s = edge_val(ei, i);
    int d = edge_val(ei, (long long)e + i);
    int pos = atomicAdd(&g_fill[d], 1);
    g_col[pos] = s;
    g_wgt[pos] = g_dinv[s] * g_dinv[d];
}

// ---------------- A prep (layer 0 only; later layers fused into k_agg) ------
__global__ void k_prep_a(const float* __restrict__ src, int n, int K, int Kpad, int stride) {
    int total = n * Kpad;
    for (int idx = blockIdx.x * blockDim.x + threadIdx.x; idx < total;
         idx += gridDim.x * blockDim.x) {
        int row = idx / Kpad, c = idx % Kpad;
        float v = (c < K) ? src[(size_t)row * stride + c] : 0.f;
        g_ap[(size_t)row * LDA + c] = __float2half(v);
    }
}

// ---------------- B prep: all 4 layers in one pass --------------------------
__global__ void k_prep_ball(const float* __restrict__ W0, const float* __restrict__ W1,
                            const float* __restrict__ W2, const float* __restrict__ W3) {
    int total = 128 * 192 + 3 * 128 * 128;   // 73728
    for (int idx = blockIdx.x * blockDim.x + threadIdx.x; idx < total;
         idx += gridDim.x * blockDim.x) {
        float w;
        if (idx < B_OFF_L1) {
            int nrow = idx / 192, k = idx % 192;
            w = (k < NF) ? W0[k * HD + nrow] : 0.f;
        } else {
            int r = idx - B_OFF_L1;
            int l = r >> 14;                 // 0..2
            int q = r & 16383;
            int nrow = q >> 7, k = q & 127;
            const float* W = (l == 0) ? W1 : ((l == 1) ? W2 : W3);
            w = W[k * HD + nrow];
        }
        g_bp[idx] = __float2half(w);
    }
}

// ---------------- WMMA GEMM: C[rows,128] = A @ B, fp16 acc/out --------------
// Output tile 128x128 per CTA, 8 warps, warp tile 32x64. ctaBase offsets rows.
__global__ __launch_bounds__(256, 3) void k_wgemm(const __half* __restrict__ Ap,
                                                  __half* __restrict__ C,
                                                  int Kpad, int ldS, int bOff, int ctaBase) {
    extern __shared__ char smem[];
    char* aBase = smem;                                  // 128 * ldS * 2
    char* bBase = smem + 128 * ldS * 2;                  // 128 * ldS * 2
    u32 aBaseU = smem_u32(aBase);
    u32 bBaseU = smem_u32(bBase);
    int tid = threadIdx.x, wid = tid >> 5;
    int row0 = (ctaBase + blockIdx.x) * 128;
    int mrow = (wid & 3) * 32;
    int ncw  = (wid >> 2) * 64;
    const __half* bp = g_bp + bOff;

    // ---- stage A tile + full B (one cp.async group) ----
    {
        int vpr = Kpad >> 3;                 // 16B vectors per row
        int nv = 128 * vpr;
        for (int q = tid; q < nv; q += 256) {
            int row = q / vpr, part = q - row * vpr;
            cp16(aBaseU + (u32)(row * ldS * 2 + part * 16),
                 Ap + (size_t)(row0 + row) * LDA + part * 8);
            cp16(bBaseU + (u32)(row * ldS * 2 + part * 16),
                 bp + (size_t)row * Kpad + part * 8);
        }
    }
    cp_commit();

    wmma::fragment<wmma::accumulator, 16, 16, 16, __half> acc[2][4];
    #pragma unroll
    for (int i = 0; i < 2; i++)
        #pragma unroll
        for (int j = 0; j < 4; j++) wmma::fill_fragment(acc[i][j], __float2half(0.f));

    cp_wait<0>();
    __syncthreads();                         // the ONLY barrier

    const __half* aSm = (const __half*)aBase;
    const __half* bSm = (const __half*)bBase;
    for (int kk = 0; kk < Kpad; kk += 16) {
        wmma::fragment<wmma::matrix_a, 16, 16, 16, __half, wmma::row_major> af[2];
        #pragma unroll
        for (int i = 0; i < 2; i++)
            wmma::load_matrix_sync(af[i], aSm + (mrow + i * 16) * ldS + kk, ldS);
        #pragma unroll
        for (int j = 0; j < 4; j++) {
            wmma::fragment<wmma::matrix_b, 16, 16, 16, __half, wmma::col_major> bfr;
            wmma::load_matrix_sync(bfr, bSm + (ncw + j * 16) * ldS + kk, ldS);
            #pragma unroll
            for (int i = 0; i < 2; i++)
                wmma::mma_sync(acc[i][j], af[i], bfr, acc[i][j]);
        }
    }

    #pragma unroll
    for (int i = 0; i < 2; i++)
        #pragma unroll
        for (int j = 0; j < 4; j++)
            wmma::store_matrix_sync(C + (size_t)(row0 + mrow + i * 16) * HD + ncw + j * 16,
                                    acc[i][j], HD, wmma::mem_row_major);
}

// ---------------- Aggregation: half-warp per node, uint4 gathers ------------
// Node range [nd0, ndEnd). mode 0: emit fp16 to g_ap. 1: fp32 out.
__global__ __launch_bounds__(256) void k_agg(const __half* __restrict__ h,
                                             const float* __restrict__ bias,
                                             float* __restrict__ out,
                                             int nd0, int ndEnd, int mode) {
    int t  = blockIdx.x * blockDim.x + threadIdx.x;
    int nd = nd0 + (t >> 4);
    int hl = t & 15;              // lane within half-warp; owns 8 cols
    if (nd >= ndEnd) return;
    int start = g_rowptr[nd];
    int cnt   = g_cnt[nd];
    int c0 = hl * 8;

    float acc[8] = {0.f, 0.f, 0.f, 0.f, 0.f, 0.f, 0.f, 0.f};
    for (int e = 0; e < cnt; e++) {
        int idx  = start + e;
        int s    = g_col[idx];
        float we = g_wgt[idx];
        union { __half2 h2[4]; uint4 u; } hv;
        hv.u = *(const uint4*)(h + (size_t)s * HD + c0);
        #pragma unroll
        for (int k = 0; k < 4; k++) {
            float2 f = __half22float2(hv.h2[k]);
            acc[2 * k]     += we * f.x;
            acc[2 * k + 1] += we * f.y;
        }
    }
    float di = g_dinv[nd];
    float d2 = di * di;
    union { __half2 h2[4]; uint4 u; } hs;
    hs.u = *(const uint4*)(h + (size_t)nd * HD + c0);
    float4 bv0 = *(const float4*)&bias[c0];
    float4 bv1 = *(const float4*)&bias[c0 + 4];
    float bb[8] = {bv0.x, bv0.y, bv0.z, bv0.w, bv1.x, bv1.y, bv1.z, bv1.w};
    #pragma unroll
    for (int k = 0; k < 4; k++) {
        float2 f = __half22float2(hs.h2[k]);
        acc[2 * k]     = tanhf(acc[2 * k]     + d2 * f.x + bb[2 * k]);
        acc[2 * k + 1] = tanhf(acc[2 * k + 1] + d2 * f.y + bb[2 * k + 1]);
    }

    if (mode == 1) {
        float4 o0 = make_float4(acc[0], acc[1], acc[2], acc[3]);
        float4 o1 = make_float4(acc[4], acc[5], acc[6], acc[7]);
        *(float4*)&out[(size_t)nd * HD + c0]     = o0;
        *(float4*)&out[(size_t)nd * HD + c0 + 4] = o1;
    } else {
        union { __half2 h2[4]; uint4 u; } o;
        #pragma unroll
        for (int k = 0; k < 4; k++)
            o.h2[k] = __floats2half2_rn(acc[2 * k], acc[2 * k + 1]);
        *(uint4*)&g_ap[(size_t)nd * LDA + c0] = o.u;
    }
}

// ---------------- launch ----------------
#define NCHUNK 4
extern "C" void kernel_launch(void* const* d_in, const int* in_sizes, int n_in,
                              void* d_out, int out_size) {
    const float* x  = (const float*)d_in[0];
    const void*  ei = d_in[1];
    const float* W0 = (const float*)d_in[2];
    const float* b0 = (const float*)d_in[3];
    const float* W1 = (const float*)d_in[4];
    const float* b1 = (const float*)d_in[5];
    const float* W2 = (const float*)d_in[6];
    const float* b2 = (const float*)d_in[7];
    const float* W3 = (const float*)d_in[8];
    const float* b3 = (const float*)d_in[9];
    float* out = (float*)d_out;

    int n  = in_sizes[0] / NF;   // 100000
    int e  = in_sizes[1] / 2;    // 1600000
    int nb = (n + 1023) / 1024;

    __half *h0, *h1, *apf;
    cudaGetSymbolAddress((void**)&h0, g_h0);
    cudaGetSymbolAddress((void**)&h1, g_h1);
    cudaGetSymbolAddress((void**)&apf, g_ap);
    const __half* ap = (const __half*)apf;

    cudaFuncSetAttribute(k_wgemm, cudaFuncAttributeMaxDynamicSharedMemorySize, 102400);

    int nCTA = (n + 127) / 128;                 // 782
    int chCTA = (nCTA + NCHUNK - 1) / NCHUNK;   // 196

    cudaStream_t s2;
    cudaStreamCreateWithFlags(&s2, cudaStreamNonBlocking);
    cudaEvent_t e1, e2, evA[3][NCHUNK], evG[3];
    cudaEventCreateWithFlags(&e1, cudaEventDisableTiming);
    cudaEventCreateWithFlags(&e2, cudaEventDisableTiming);
    for (int b = 0; b < 3; b++) {
        cudaEventCreateWithFlags(&evG[b], cudaEventDisableTiming);
        for (int c = 0; c < NCHUNK; c++)
            cudaEventCreateWithFlags(&evA[b][c], cudaEventDisableTiming);
    }

    // root: probe + zero counters
    k_probe_zero<<<(n + 255) / 256, 256>>>((const int*)ei, n);
    cudaEventRecord(e1, 0);
    cudaStreamWaitEvent(s2, e1, 0);

    // branch A: preps + layer-0 GEMM -> h0
    k_prep_a<<<1024, 256>>>(x, n, NF, 192, NF);
    k_prep_ball<<<288, 256>>>(W0, W1, W2, W3);
    k_wgemm<<<nCTA, 256, 102400>>>(ap, h0, 192, 200, B_OFF_L0, 0);

    // branch B (s2): CSR build
    k_count<<<(e + 255) / 256, 256, 0, s2>>>(ei, e);
    k_scan1<<<nb, 1024, 0, s2>>>(n);
    k_scan2<<<1, 32, 0, s2>>>(nb);
    k_scan3<<<(n + 255) / 256, 256, 0, s2>>>(n);
    k_fill<<<(e + 255) / 256, 256, 0, s2>>>(ei, e);
    cudaEventRecord(e2, s2);
    cudaStreamWaitEvent(0, e2, 0);

    // boundaries: agg (layer L) chunks on stream0, gemm (L+1) chunks on s2
    const __half* hs[4] = {(const __half*)h0, (const __half*)h1, (const __half*)h0, (const __half*)h1};
    __half* hd[3] = {h1, h0, h1};
    const float* bias[4] = {b0, b1, b2, b3};
    int bOff[3] = {B_OFF_L1, B_OFF_L2, B_OFF_L3};

    for (int b = 0; b < 3; b++) {
        for (int c = 0; c < NCHUNK; c++) {
            int base = c * chCTA;
            int ctas = (base + chCTA <= nCTA) ? chCTA : (nCTA - base);
            if (ctas <= 0) continue;
            int nd0 = base * 128;
            int ndEnd = (nd0 + ctas * 128 < n) ? nd0 + ctas * 128 : n;
            int ablk = ((ndEnd - nd0) * 16 + 255) / 256;
            k_agg<<<ablk, 256>>>(hs[b], bias[b], out, nd0, ndEnd, 0);
            cudaEventRecord(evA[b][c], 0);
            cudaStreamWaitEvent(s2, evA[b][c], 0);
            k_wgemm<<<ctas, 256, 69632, s2>>>(ap, hd[b], HD, 136, bOff[b], base);
        }
        cudaEventRecord(evG[b], s2);
        cudaStreamWaitEvent(0, evG[b], 0);
    }

    // final aggregate (mode 1) -> out
    k_agg<<<(n * 16 + 255) / 256, 256>>>(hs[3], bias[3], out, 0, n, 1);
}

// round 16
// speedup vs baseline: 1.0728x; 1.0728x over previous
#include <cuda_runtime.h>
#include <cuda_bf16.h>
#include <cuda_fp16.h>
#include <mma.h>
#include <math.h>

using namespace nvcuda;

#define NN 100000
#define EE 1600000
#define NF 133
#define HD 128
#define NROWS 100096           // NN rounded up to 128
#define LDA 192                // g_ap row stride in elems (layer-0 Kpad)

typedef unsigned long long ull;
typedef unsigned int u32;

// ---------------- device scratch (static, no runtime alloc) ----------------
__device__ __half g_h0[(size_t)NROWS * HD];          // activations ping
__device__ __half g_h1[(size_t)NROWS * HD];          // activations pong
__device__ __half g_ap[(size_t)NROWS * LDA];         // layer-0 fp16 input
__device__ __half g_bp[128 * 192 + 3 * 128 * 128];   // B regions: L0 | L1 | L2 | L3
__device__ float g_dinv[NN];
__device__ int   g_cnt[NN];
__device__ int   g_rowptr[NN];
__device__ int   g_fill[NN];
__device__ int   g_col[EE];
__device__ float g_wgt[EE];
__device__ int   g_bsum[256];
__device__ int   g_is64;

#define B_OFF_L0 0
#define B_OFF_L1 24576
#define B_OFF_L2 40960
#define B_OFF_L3 57344

// ---------------- cp.async helpers ----------------
__device__ __forceinline__ u32 smem_u32(const void* p) {
    u32 a;
    asm("{ .reg .u64 t; cvta.to.shared.u64 t, %1; cvt.u32.u64 %0, t; }" : "=r"(a) : "l"(p));
    return a;
}
__device__ __forceinline__ void cp16(u32 dst, const void* src) {
    asm volatile("cp.async.cg.shared.global [%0], [%1], 16;" :: "r"(dst), "l"(src));
}
__device__ __forceinline__ void cp_commit() {
    asm volatile("cp.async.commit_group;");
}
template <int N>
__device__ __forceinline__ void cp_wait() {
    asm volatile("cp.async.wait_group %0;" :: "n"(N));
}

// ---------------- probe + zero counters (merged) ----------------
__global__ void k_probe_zero(const int* __restrict__ ei, int n) {
    int i = blockIdx.x * blockDim.x + threadIdx.x;
    if (blockIdx.x == 0) {
        __shared__ int nz;
        if (threadIdx.x == 0) nz = 0;
        __syncthreads();
        int v = ei[threadIdx.x * 2 + 1];
        if (v != 0) atomicAdd(&nz, 1);
        __syncthreads();
        if (threadIdx.x == 0) g_is64 = (nz == 0) ? 1 : 0;
    }
    if (i < n) g_cnt[i] = 0;
}

__device__ __forceinline__ int edge_val(const void* ei, long long idx) {
    if (g_is64) return (int)((const long long*)ei)[idx];
    return ((const int*)ei)[idx];
}

// ---------------- CSR build ----------------
__global__ void k_count(const void* __restrict__ ei, int e) {
    int i = blockIdx.x * blockDim.x + threadIdx.x;
    if (i >= e) return;
    int d = edge_val(ei, (long long)e + i);
    atomicAdd(&g_cnt[d], 1);
}

__global__ void k_scan1(int n) {
    __shared__ int s[1024];
    int t = threadIdx.x;
    int i = blockIdx.x * 1024 + t;
    int v = (i < n) ? g_cnt[i] : 0;
    s[t] = v;
    __syncthreads();
    #pragma unroll
    for (int off = 1; off < 1024; off <<= 1) {
        int x = (t >= off) ? s[t - off] : 0;
        __syncthreads();
        s[t] += x;
        __syncthreads();
    }
    if (i < n) g_rowptr[i] = s[t] - v;
    if (t == 1023) g_bsum[blockIdx.x] = s[1023];
}

__global__ void k_scan2(int nb) {
    if (threadIdx.x == 0) {
        int run = 0;
        for (int b = 0; b < nb; b++) { int t = g_bsum[b]; g_bsum[b] = run; run += t; }
    }
}

__global__ void k_scan3(int n) {
    int i = blockIdx.x * blockDim.x + threadIdx.x;
    if (i >= n) return;
    int r = g_rowptr[i] + g_bsum[i >> 10];
    g_rowptr[i] = r;
    g_fill[i]   = r;
    g_dinv[i]   = rsqrtf((float)g_cnt[i] + 1.0f);
}

__global__ void k_fill(const void* __restrict__ ei, int e) {
    int i = blockIdx.x * blockDim.x + threadIdx.x;
    if (i >= e) return;
    int s = edge_val(ei, i);
    int d = edge_val(ei, (long long)e + i);
    int pos = atomicAdd(&g_fill[d], 1);
    g_col[pos] = s;
    g_wgt[pos] = g_dinv[s] * g_dinv[d];
}

// ---------------- A prep (layer 0 only) ----------------
__global__ void k_prep_a(const float* __restrict__ src, int n, int K, int Kpad, int stride) {
    int total = n * Kpad;
    for (int idx = blockIdx.x * blockDim.x + threadIdx.x; idx < total;
         idx += gridDim.x * blockDim.x) {
        int row = idx / Kpad, c = idx % Kpad;
        float v = (c < K) ? src[(size_t)row * stride + c] : 0.f;
        g_ap[(size_t)row * LDA + c] = __float2half(v);
    }
}

// ---------------- B prep: all 4 layers in one pass --------------------------
__global__ void k_prep_ball(const float* __restrict__ W0, const float* __restrict__ W1,
                            const float* __restrict__ W2, const float* __restrict__ W3) {
    int total = 128 * 192 + 3 * 128 * 128;   // 73728
    for (int idx = blockIdx.x * blockDim.x + threadIdx.x; idx < total;
         idx += gridDim.x * blockDim.x) {
        float w;
        if (idx < B_OFF_L1) {
            int nrow = idx / 192, k = idx % 192;
            w = (k < NF) ? W0[k * HD + nrow] : 0.f;
        } else {
            int r = idx - B_OFF_L1;
            int l = r >> 14;                 // 0..2
            int q = r & 16383;
            int nrow = q >> 7, k = q & 127;
            const float* W = (l == 0) ? W1 : ((l == 1) ? W2 : W3);
            w = W[k * HD + nrow];
        }
        g_bp[idx] = __float2half(w);
    }
}

// ---------------- WMMA GEMM (layer 0): C = A @ B, fp16 acc/out --------------
__global__ __launch_bounds__(256, 3) void k_wgemm(const __half* __restrict__ Ap,
                                                  __half* __restrict__ C,
                                                  int Kpad, int ldS, int bOff) {
    extern __shared__ char smem[];
    char* aBase = smem;
    char* bBase = smem + 128 * ldS * 2;
    u32 aBaseU = smem_u32(aBase);
    u32 bBaseU = smem_u32(bBase);
    int tid = threadIdx.x, wid = tid >> 5;
    int row0 = blockIdx.x * 128;
    int mrow = (wid & 3) * 32;
    int ncw  = (wid >> 2) * 64;
    const __half* bp = g_bp + bOff;

    {
        int vpr = Kpad >> 3;
        int nv = 128 * vpr;
        for (int q = tid; q < nv; q += 256) {
            int row = q / vpr, part = q - row * vpr;
            cp16(aBaseU + (u32)(row * ldS * 2 + part * 16),
                 Ap + (size_t)(row0 + row) * LDA + part * 8);
            cp16(bBaseU + (u32)(row * ldS * 2 + part * 16),
                 bp + (size_t)row * Kpad + part * 8);
        }
    }
    cp_commit();

    wmma::fragment<wmma::accumulator, 16, 16, 16, __half> acc[2][4];
    #pragma unroll
    for (int i = 0; i < 2; i++)
        #pragma unroll
        for (int j = 0; j < 4; j++) wmma::fill_fragment(acc[i][j], __float2half(0.f));

    cp_wait<0>();
    __syncthreads();

    const __half* aSm = (const __half*)aBase;
    const __half* bSm = (const __half*)bBase;
    for (int kk = 0; kk < Kpad; kk += 16) {
        wmma::fragment<wmma::matrix_a, 16, 16, 16, __half, wmma::row_major> af[2];
        #pragma unroll
        for (int i = 0; i < 2; i++)
            wmma::load_matrix_sync(af[i], aSm + (mrow + i * 16) * ldS + kk, ldS);
        #pragma unroll
        for (int j = 0; j < 4; j++) {
            wmma::fragment<wmma::matrix_b, 16, 16, 16, __half, wmma::col_major> bfr;
            wmma::load_matrix_sync(bfr, bSm + (ncw + j * 16) * ldS + kk, ldS);
            #pragma unroll
            for (int i = 0; i < 2; i++)
                wmma::mma_sync(acc[i][j], af[i], bfr, acc[i][j]);
        }
    }

    #pragma unroll
    for (int i = 0; i < 2; i++)
        #pragma unroll
        for (int j = 0; j < 4; j++)
            wmma::store_matrix_sync(C + (size_t)(row0 + mrow + i * 16) * HD + ncw + j * 16,
                                    acc[i][j], HD, wmma::mem_row_major);
}

// ---------------- FUSED agg(L) + GEMM(L+1) per 128-row tile -----------------
// Phase 1: gather+tanh for this CTA's 128 nodes -> smem A tile (fp16, ld 136).
// Phase 2: WMMA A(smem) @ B(smem, streamed at entry) -> direct fp16 store.
#define FLD 136
__global__ __launch_bounds__(256, 3) void k_aggemm(const __half* __restrict__ hIn,
                                                   const float* __restrict__ bias,
                                                   __half* __restrict__ hOut,
                                                   int n, int bOff) {
    extern __shared__ char smem[];
    __half* aSm = (__half*)smem;                        // 128 x FLD
    __half* bSm = (__half*)(smem + 128 * FLD * 2);      // 128 x FLD
    u32 bBaseU = smem_u32(bSm);
    int tid = threadIdx.x, wid = tid >> 5;
    int row0 = blockIdx.x * 128;
    const __half* bp = g_bp + bOff;

    // kick off B staging (overlaps with the gather phase)
    for (int q = tid; q < 2048; q += 256) {
        int row = q >> 4, part = q & 15;
        cp16(bBaseU + (u32)(row * (FLD * 2) + part * 16),
             bp + (size_t)row * HD + part * 8);
    }
    cp_commit();

    // ---- phase 1: aggregation into smem A ----
    int hw = tid >> 4;            // half-warp 0..15
    int hl = tid & 15;            // lane in half-warp
    int c0 = hl * 8;
    for (int p = 0; p < 8; p++) {
        int ndl = hw * 8 + p;     // local row 0..127
        int nd = row0 + ndl;
        union { __half2 h2[4]; uint4 u; } o;
        if (nd < n) {
            int start = g_rowptr[nd];
            int cnt   = g_cnt[nd];
            float acc[8] = {0.f, 0.f, 0.f, 0.f, 0.f, 0.f, 0.f, 0.f};
            int ee = 0;
            for (; ee + 2 <= cnt; ee += 2) {
                int i0 = start + ee, i1 = start + ee + 1;
                int s0 = g_col[i0], s1 = g_col[i1];
                float w0 = g_wgt[i0], w1 = g_wgt[i1];
                union { __half2 h2[4]; uint4 u; } v0, v1;
                v0.u = *(const uint4*)(hIn + (size_t)s0 * HD + c0);
                v1.u = *(const uint4*)(hIn + (size_t)s1 * HD + c0);
                #pragma unroll
                for (int k = 0; k < 4; k++) {
                    float2 f0 = __half22float2(v0.h2[k]);
                    float2 f1 = __half22float2(v1.h2[k]);
                    acc[2 * k]     += w0 * f0.x + w1 * f1.x;
                    acc[2 * k + 1] += w0 * f0.y + w1 * f1.y;
                }
            }
            for (; ee < cnt; ee++) {
                int idx = start + ee;
                int s = g_col[idx];
                float we = g_wgt[idx];
                union { __half2 h2[4]; uint4 u; } hv;
                hv.u = *(const uint4*)(hIn + (size_t)s * HD + c0);
                #pragma unroll
                for (int k = 0; k < 4; k++) {
                    float2 f = __half22float2(hv.h2[k]);
                    acc[2 * k]     += we * f.x;
                    acc[2 * k + 1] += we * f.y;
                }
            }
            float di = g_dinv[nd];
            float d2 = di * di;
            union { __half2 h2[4]; uint4 u; } hs;
            hs.u = *(const uint4*)(hIn + (size_t)nd * HD + c0);
            float4 bv0 = *(const float4*)&bias[c0];
            float4 bv1 = *(const float4*)&bias[c0 + 4];
            float bb[8] = {bv0.x, bv0.y, bv0.z, bv0.w, bv1.x, bv1.y, bv1.z, bv1.w};
            #pragma unroll
            for (int k = 0; k < 4; k++) {
                float2 f = __half22float2(hs.h2[k]);
                o.h2[k] = __floats2half2_rn(tanhf(acc[2 * k]     + d2 * f.x + bb[2 * k]),
                                            tanhf(acc[2 * k + 1] + d2 * f.y + bb[2 * k + 1]));
            }
        } else {
            o.u = make_uint4(0, 0, 0, 0);
        }
        *(uint4*)&aSm[ndl * FLD + c0] = o.u;
    }

    cp_wait<0>();
    __syncthreads();

    // ---- phase 2: WMMA ----
    int mrow = (wid & 3) * 32;
    int ncw  = (wid >> 2) * 64;
    wmma::fragment<wmma::accumulator, 16, 16, 16, __half> acc[2][4];
    #pragma unroll
    for (int i = 0; i < 2; i++)
        #pragma unroll
        for (int j = 0; j < 4; j++) wmma::fill_fragment(acc[i][j], __float2half(0.f));

    for (int kk = 0; kk < HD; kk += 16) {
        wmma::fragment<wmma::matrix_a, 16, 16, 16, __half, wmma::row_major> af[2];
        #pragma unroll
        for (int i = 0; i < 2; i++)
            wmma::load_matrix_sync(af[i], aSm + (mrow + i * 16) * FLD + kk, FLD);
        #pragma unroll
        for (int j = 0; j < 4; j++) {
            wmma::fragment<wmma::matrix_b, 16, 16, 16, __half, wmma::col_major> bfr;
            wmma::load_matrix_sync(bfr, bSm + (ncw + j * 16) * FLD + kk, FLD);
            #pragma unroll
            for (int i = 0; i < 2; i++)
                wmma::mma_sync(acc[i][j], af[i], bfr, acc[i][j]);
        }
    }

    #pragma unroll
    for (int i = 0; i < 2; i++)
        #pragma unroll
        for (int j = 0; j < 4; j++)
            wmma::store_matrix_sync(hOut + (size_t)(row0 + mrow + i * 16) * HD + ncw + j * 16,
                                    acc[i][j], HD, wmma::mem_row_major);
}

// ---------------- Final aggregation (fp32 out) ------------------------------
__global__ __launch_bounds__(256) void k_agg(const __half* __restrict__ h,
                                             const float* __restrict__ bias,
                                             float* __restrict__ out, int n) {
    int t  = blockIdx.x * blockDim.x + threadIdx.x;
    int nd = t >> 4;
    int hl = t & 15;
    if (nd >= n) return;
    int start = g_rowptr[nd];
    int cnt   = g_cnt[nd];
    int c0 = hl * 8;

    float acc[8] = {0.f, 0.f, 0.f, 0.f, 0.f, 0.f, 0.f, 0.f};
    for (int e = 0; e < cnt; e++) {
        int idx  = start + e;
        int s    = g_col[idx];
        float we = g_wgt[idx];
        union { __half2 h2[4]; uint4 u; } hv;
        hv.u = *(const uint4*)(h + (size_t)s * HD + c0);
        #pragma unroll
        for (int k = 0; k < 4; k++) {
            float2 f = __half22float2(hv.h2[k]);
            acc[2 * k]     += we * f.x;
            acc[2 * k + 1] += we * f.y;
        }
    }
    float di = g_dinv[nd];
    float d2 = di * di;
    union { __half2 h2[4]; uint4 u; } hs;
    hs.u = *(const uint4*)(h + (size_t)nd * HD + c0);
    float4 bv0 = *(const float4*)&bias[c0];
    float4 bv1 = *(const float4*)&bias[c0 + 4];
    float bb[8] = {bv0.x, bv0.y, bv0.z, bv0.w, bv1.x, bv1.y, bv1.z, bv1.w};
    float4 o0, o1;
    {
        float2 f0 = __half22float2(hs.h2[0]);
        float2 f1 = __half22float2(hs.h2[1]);
        float2 f2 = __half22float2(hs.h2[2]);
        float2 f3 = __half22float2(hs.h2[3]);
        o0.x = tanhf(acc[0] + d2 * f0.x + bb[0]);
        o0.y = tanhf(acc[1] + d2 * f0.y + bb[1]);
        o0.z = tanhf(acc[2] + d2 * f1.x + bb[2]);
        o0.w = tanhf(acc[3] + d2 * f1.y + bb[3]);
        o1.x = tanhf(acc[4] + d2 * f2.x + bb[4]);
        o1.y = tanhf(acc[5] + d2 * f2.y + bb[5]);
        o1.z = tanhf(acc[6] + d2 * f3.x + bb[6]);
        o1.w = tanhf(acc[7] + d2 * f3.y + bb[7]);
    }
    *(float4*)&out[(size_t)nd * HD + c0]     = o0;
    *(float4*)&out[(size_t)nd * HD + c0 + 4] = o1;
}

// ---------------- launch ----------------
extern "C" void kernel_launch(void* const* d_in, const int* in_sizes, int n_in,
                              void* d_out, int out_size) {
    const float* x  = (const float*)d_in[0];
    const void*  ei = d_in[1];
    const float* W0 = (const float*)d_in[2];
    const float* b0 = (const float*)d_in[3];
    const float* W1 = (const float*)d_in[4];
    const float* b1 = (const float*)d_in[5];
    const float* W2 = (const float*)d_in[6];
    const float* b2 = (const float*)d_in[7];
    const float* W3 = (const float*)d_in[8];
    const float* b3 = (const float*)d_in[9];
    float* out = (float*)d_out;

    int n  = in_sizes[0] / NF;   // 100000
    int e  = in_sizes[1] / 2;    // 1600000
    int nb = (n + 1023) / 1024;

    __half *h0, *h1, *apf;
    cudaGetSymbolAddress((void**)&h0, g_h0);
    cudaGetSymbolAddress((void**)&h1, g_h1);
    cudaGetSymbolAddress((void**)&apf, g_ap);
    const __half* ap = (const __half*)apf;

    cudaFuncSetAttribute(k_wgemm, cudaFuncAttributeMaxDynamicSharedMemorySize, 102400);
    cudaFuncSetAttribute(k_aggemm, cudaFuncAttributeMaxDynamicSharedMemorySize, 69632);

    int nCTA = (n + 127) / 128;                 // 782
    int agg_blocks = (n * 16 + 255) / 256;      // 6250

    // ---- capture fork: CSR on s2 concurrent with prep + GEMM L0 ----
    cudaStream_t s2;
    cudaStreamCreateWithFlags(&s2, cudaStreamNonBlocking);
    cudaEvent_t e1, e2;
    cudaEventCreateWithFlags(&e1, cudaEventDisableTiming);
    cudaEventCreateWithFlags(&e2, cudaEventDisableTiming);

    k_probe_zero<<<(n + 255) / 256, 256>>>((const int*)ei, n);
    cudaEventRecord(e1, 0);
    cudaStreamWaitEvent(s2, e1, 0);

    // branch A: preps + layer-0 GEMM -> h0
    k_prep_a<<<1024, 256>>>(x, n, NF, 192, NF);
    k_prep_ball<<<288, 256>>>(W0, W1, W2, W3);
    k_wgemm<<<nCTA, 256, 102400>>>(ap, h0, 192, 200, B_OFF_L0);

    // branch B (s2): CSR build
    k_count<<<(e + 255) / 256, 256, 0, s2>>>(ei, e);
    k_scan1<<<nb, 1024, 0, s2>>>(n);
    k_scan2<<<1, 32, 0, s2>>>(nb);
    k_scan3<<<(n + 255) / 256, 256, 0, s2>>>(n);
    k_fill<<<(e + 255) / 256, 256, 0, s2>>>(ei, e);
    cudaEventRecord(e2, s2);
    cudaStreamWaitEvent(0, e2, 0);

    // fused agg+GEMM boundaries, then final agg
    k_aggemm<<<nCTA, 256, 69632>>>((const __half*)h0, b0, h1, n, B_OFF_L1);
    k_aggemm<<<nCTA, 256, 69632>>>((const __half*)h1, b1, h0, n, B_OFF_L2);
    k_aggemm<<<nCTA, 256, 69632>>>((const __half*)h0, b2, h1, n, B_OFF_L3);
    k_agg<<<agg_blocks, 256>>>((const __half*)h1, b3, out, n);
}

// round 17
// speedup vs baseline: 1.2240x; 1.1410x over previous
#include <cuda_runtime.h>
#include <cuda_bf16.h>
#include <cuda_fp16.h>
#include <mma.h>
#include <math.h>

using namespace nvcuda;

#define NN 100000
#define EE 1600000
#define NF 133
#define HD 128
#define NROWS 100096           // NN rounded up to 128
#define LDA 144                // g_ap row stride in elems (layer-0 Kpad)

typedef unsigned long long ull;
typedef unsigned int u32;

// ---------------- device scratch (static, no runtime alloc) ----------------
__device__ __half g_h0[(size_t)NROWS * HD];          // activations ping
__device__ __half g_h1[(size_t)NROWS * HD];          // activations pong
__device__ __half g_ap[(size_t)NROWS * LDA];         // fp16 GEMM input
__device__ __half g_bp[128 * 144 + 3 * 128 * 128];   // B regions: L0 | L1 | L2 | L3
__device__ float g_dinv[NN];
__device__ int   g_cnt[NN];
__device__ int   g_rowptr[NN];
__device__ int   g_fill[NN];
__device__ int   g_col[EE];
__device__ float g_wgt[EE];
__device__ int   g_bsum[256];
__device__ int   g_is64;

#define B_OFF_L0 0
#define B_OFF_L1 18432
#define B_OFF_L2 34816
#define B_OFF_L3 51200

// ---------------- cp.async helpers ----------------
__device__ __forceinline__ u32 smem_u32(const void* p) {
    u32 a;
    asm("{ .reg .u64 t; cvta.to.shared.u64 t, %1; cvt.u32.u64 %0, t; }" : "=r"(a) : "l"(p));
    return a;
}
__device__ __forceinline__ void cp16(u32 dst, const void* src) {
    asm volatile("cp.async.cg.shared.global [%0], [%1], 16;" :: "r"(dst), "l"(src));
}
__device__ __forceinline__ void cp_commit() {
    asm volatile("cp.async.commit_group;");
}
template <int N>
__device__ __forceinline__ void cp_wait() {
    asm volatile("cp.async.wait_group %0;" :: "n"(N));
}

// ---------------- probe + zero counters (merged) ----------------
__global__ void k_probe_zero(const int* __restrict__ ei, int n) {
    int i = blockIdx.x * blockDim.x + threadIdx.x;
    if (blockIdx.x == 0) {
        __shared__ int nz;
        if (threadIdx.x == 0) nz = 0;
        __syncthreads();
        int v = ei[threadIdx.x * 2 + 1];
        if (v != 0) atomicAdd(&nz, 1);
        __syncthreads();
        if (threadIdx.x == 0) g_is64 = (nz == 0) ? 1 : 0;
    }
    if (i < n) g_cnt[i] = 0;
}

__device__ __forceinline__ int edge_val(const void* ei, long long idx) {
    if (g_is64) return (int)((const long long*)ei)[idx];
    return ((const int*)ei)[idx];
}

// ---------------- CSR build ----------------
__global__ void k_count(const void* __restrict__ ei, int e) {
    int i = blockIdx.x * blockDim.x + threadIdx.x;
    if (i >= e) return;
    int d = edge_val(ei, (long long)e + i);
    atomicAdd(&g_cnt[d], 1);
}

__global__ void k_scan1(int n) {
    __shared__ int s[1024];
    int t = threadIdx.x;
    int i = blockIdx.x * 1024 + t;
    int v = (i < n) ? g_cnt[i] : 0;
    s[t] = v;
    __syncthreads();
    #pragma unroll
    for (int off = 1; off < 1024; off <<= 1) {
        int x = (t >= off) ? s[t - off] : 0;
        __syncthreads();
        s[t] += x;
        __syncthreads();
    }
    if (i < n) g_rowptr[i] = s[t] - v;
    if (t == 1023) g_bsum[blockIdx.x] = s[1023];
}

__global__ void k_scan2(int nb) {
    if (threadIdx.x == 0) {
        int run = 0;
        for (int b = 0; b < nb; b++) { int t = g_bsum[b]; g_bsum[b] = run; run += t; }
    }
}

__global__ void k_scan3(int n) {
    int i = blockIdx.x * blockDim.x + threadIdx.x;
    if (i >= n) return;
    int r = g_rowptr[i] + g_bsum[i >> 10];
    g_rowptr[i] = r;
    g_fill[i]   = r;
    g_dinv[i]   = rsqrtf((float)g_cnt[i] + 1.0f);
}

__global__ void k_fill(const void* __restrict__ ei, int e) {
    int i = blockIdx.x * blockDim.x + threadIdx.x;
    if (i >= e) return;
    int s = edge_val(ei, i);
    int d = edge_val(ei, (long long)e + i);
    int pos = atomicAdd(&g_fill[d], 1);
    g_col[pos] = s;
    g_wgt[pos] = g_dinv[s] * g_dinv[d];
}

// ---------------- A prep (layer 0 only) ----------------
__global__ void k_prep_a(const float* __restrict__ src, int n, int K, int Kpad, int stride) {
    int total = n * Kpad;
    for (int idx = blockIdx.x * blockDim.x + threadIdx.x; idx < total;
         idx += gridDim.x * blockDim.x) {
        int row = idx / Kpad, c = idx % Kpad;
        float v = (c < K) ? src[(size_t)row * stride + c] : 0.f;
        g_ap[(size_t)row * LDA + c] = __float2half(v);
    }
}

// ---------------- B prep: all 4 layers in one pass --------------------------
// region L0: [128][144] from W0 (K=133, zero-padded); L1-3: [128][128].
__global__ void k_prep_ball(const float* __restrict__ W0, const float* __restrict__ W1,
                            const float* __restrict__ W2, const float* __restrict__ W3) {
    int total = 128 * 144 + 3 * 128 * 128;   // 67584
    for (int idx = blockIdx.x * blockDim.x + threadIdx.x; idx < total;
         idx += gridDim.x * blockDim.x) {
        float w;
        if (idx < B_OFF_L1) {
            int nrow = idx / 144, k = idx % 144;
            w = (k < NF) ? W0[k * HD + nrow] : 0.f;
        } else {
            int r = idx - B_OFF_L1;
            int l = r >> 14;                 // 0..2
            int q = r & 16383;
            int nrow = q >> 7, k = q & 127;
            const float* W = (l == 0) ? W1 : ((l == 1) ? W2 : W3);
            w = W[k * HD + nrow];
        }
        g_bp[idx] = __float2half(w);
    }
}

// ---------------- WMMA GEMM: C[n,128] = A[n,K] @ B[K,128], fp16 acc/out -----
// Grid 782: output tile 128x128 per CTA, 8 warps, warp tile 32x64.
// A tile + full B staged to smem in ONE cp.async group; one barrier total.
__global__ __launch_bounds__(256, 3) void k_wgemm(const __half* __restrict__ Ap,
                                                  __half* __restrict__ C,
                                                  int Kpad, int ldS, int bOff) {
    extern __shared__ char smem[];
    char* aBase = smem;
    char* bBase = smem + 128 * ldS * 2;
    u32 aBaseU = smem_u32(aBase);
    u32 bBaseU = smem_u32(bBase);
    int tid = threadIdx.x, wid = tid >> 5;
    int row0 = blockIdx.x * 128;
    int mrow = (wid & 3) * 32;
    int ncw  = (wid >> 2) * 64;
    const __half* bp = g_bp + bOff;

    {
        int vpr = Kpad >> 3;
        int nv = 128 * vpr;
        for (int q = tid; q < nv; q += 256) {
            int row = q / vpr, part = q - row * vpr;
            cp16(aBaseU + (u32)(row * ldS * 2 + part * 16),
                 Ap + (size_t)(row0 + row) * LDA + part * 8);
            cp16(bBaseU + (u32)(row * ldS * 2 + part * 16),
                 bp + (size_t)row * Kpad + part * 8);
        }
    }
    cp_commit();

    wmma::fragment<wmma::accumulator, 16, 16, 16, __half> acc[2][4];
    #pragma unroll
    for (int i = 0; i < 2; i++)
        #pragma unroll
        for (int j = 0; j < 4; j++) wmma::fill_fragment(acc[i][j], __float2half(0.f));

    cp_wait<0>();
    __syncthreads();

    const __half* aSm = (const __half*)aBase;
    const __half* bSm = (const __half*)bBase;
    for (int kk = 0; kk < Kpad; kk += 16) {
        wmma::fragment<wmma::matrix_a, 16, 16, 16, __half, wmma::row_major> af[2];
        #pragma unroll
        for (int i = 0; i < 2; i++)
            wmma::load_matrix_sync(af[i], aSm + (mrow + i * 16) * ldS + kk, ldS);
        #pragma unroll
        for (int j = 0; j < 4; j++) {
            wmma::fragment<wmma::matrix_b, 16, 16, 16, __half, wmma::col_major> bfr;
            wmma::load_matrix_sync(bfr, bSm + (ncw + j * 16) * ldS + kk, ldS);
            #pragma unroll
            for (int i = 0; i < 2; i++)
                wmma::mma_sync(acc[i][j], af[i], bfr, acc[i][j]);
        }
    }

    #pragma unroll
    for (int i = 0; i < 2; i++)
        #pragma unroll
        for (int j = 0; j < 4; j++)
            wmma::store_matrix_sync(C + (size_t)(row0 + mrow + i * 16) * HD + ncw + j * 16,
                                    acc[i][j], HD, wmma::mem_row_major);
}

// ---------------- Aggregation: half-warp per node, uint4 gathers, 2x unroll -
// mode 0: emit fp16 to g_ap. mode 1: fp32 out.
__global__ __launch_bounds__(256) void k_agg(const __half* __restrict__ h,
                                             const float* __restrict__ bias,
                                             float* __restrict__ out, int n, int mode) {
    int t  = blockIdx.x * blockDim.x + threadIdx.x;
    int nd = t >> 4;              // node (half-warp)
    int hl = t & 15;              // lane within half-warp; owns 8 cols
    if (nd >= n) return;
    int start = g_rowptr[nd];
    int cnt   = g_cnt[nd];
    int c0 = hl * 8;

    float acc[8] = {0.f, 0.f, 0.f, 0.f, 0.f, 0.f, 0.f, 0.f};
    int ee = 0;
    for (; ee + 2 <= cnt; ee += 2) {
        int i0 = start + ee, i1 = start + ee + 1;
        int s0 = g_col[i0], s1 = g_col[i1];
        float w0 = g_wgt[i0], w1 = g_wgt[i1];
        union { __half2 h2[4]; uint4 u; } v0, v1;
        v0.u = *(const uint4*)(h + (size_t)s0 * HD + c0);
        v1.u = *(const uint4*)(h + (size_t)s1 * HD + c0);
        #pragma unroll
        for (int k = 0; k < 4; k++) {
            float2 f0 = __half22float2(v0.h2[k]);
            float2 f1 = __half22float2(v1.h2[k]);
            acc[2 * k]     += w0 * f0.x + w1 * f1.x;
            acc[2 * k + 1] += w0 * f0.y + w1 * f1.y;
        }
    }
    for (; ee < cnt; ee++) {
        int idx = start + ee;
        int s = g_col[idx];
        float we = g_wgt[idx];
        union { __half2 h2[4]; uint4 u; } hv;
        hv.u = *(const uint4*)(h + (size_t)s * HD + c0);
        #pragma unroll
        for (int k = 0; k < 4; k++) {
            float2 f = __half22float2(hv.h2[k]);
            acc[2 * k]     += we * f.x;
            acc[2 * k + 1] += we * f.y;
        }
    }
    float di = g_dinv[nd];
    float d2 = di * di;
    union { __half2 h2[4]; uint4 u; } hs;
    hs.u = *(const uint4*)(h + (size_t)nd * HD + c0);
    float4 bv0 = *(const float4*)&bias[c0];
    float4 bv1 = *(const float4*)&bias[c0 + 4];
    float bb[8] = {bv0.x, bv0.y, bv0.z, bv0.w, bv1.x, bv1.y, bv1.z, bv1.w};
    #pragma unroll
    for (int k = 0; k < 4; k++) {
        float2 f = __half22float2(hs.h2[k]);
        acc[2 * k]     = tanhf(acc[2 * k]     + d2 * f.x + bb[2 * k]);
        acc[2 * k + 1] = tanhf(acc[2 * k + 1] + d2 * f.y + bb[2 * k + 1]);
    }

    if (mode == 1) {
        float4 o0 = make_float4(acc[0], acc[1], acc[2], acc[3]);
        float4 o1 = make_float4(acc[4], acc[5], acc[6], acc[7]);
        *(float4*)&out[(size_t)nd * HD + c0]     = o0;
        *(float4*)&out[(size_t)nd * HD + c0 + 4] = o1;
    } else {
        union { __half2 h2[4]; uint4 u; } o;
        #pragma unroll
        for (int k = 0; k < 4; k++)
            o.h2[k] = __floats2half2_rn(acc[2 * k], acc[2 * k + 1]);
        *(uint4*)&g_ap[(size_t)nd * LDA + c0] = o.u;
    }
}

// ---------------- launch ----------------
extern "C" void kernel_launch(void* const* d_in, const int* in_sizes, int n_in,
                              void* d_out, int out_size) {
    const float* x  = (const float*)d_in[0];
    const void*  ei = d_in[1];
    const float* W0 = (const float*)d_in[2];
    const float* b0 = (const float*)d_in[3];
    const float* W1 = (const float*)d_in[4];
    const float* b1 = (const float*)d_in[5];
    const float* W2 = (const float*)d_in[6];
    const float* b2 = (const float*)d_in[7];
    const float* W3 = (const float*)d_in[8];
    const float* b3 = (const float*)d_in[9];
    float* out = (float*)d_out;

    int n  = in_sizes[0] / NF;   // 100000
    int e  = in_sizes[1] / 2;    // 1600000
    int nb = (n + 1023) / 1024;

    __half *h0, *apf;
    cudaGetSymbolAddress((void**)&h0, g_h0);
    cudaGetSymbolAddress((void**)&apf, g_ap);
    const __half* ap = (const __half*)apf;

    // smem: L0 = 2*128*152*2 = 77824 ; L1-3 = 2*128*136*2 = 69632
    cudaFuncSetAttribute(k_wgemm, cudaFuncAttributeMaxDynamicSharedMemorySize, 77824);

    int nCTA = (n + 127) / 128;                 // 782
    int agg_blocks = (n * 16 + 255) / 256;      // 6250

    // ---- capture fork: CSR on s2 concurrent with prep + GEMM L0 ----
    cudaStream_t s2;
    cudaStreamCreateWithFlags(&s2, cudaStreamNonBlocking);
    cudaEvent_t e1, e2;
    cudaEventCreateWithFlags(&e1, cudaEventDisableTiming);
    cudaEventCreateWithFlags(&e2, cudaEventDisableTiming);

    k_probe_zero<<<(n + 255) / 256, 256>>>((const int*)ei, n);
    cudaEventRecord(e1, 0);
    cudaStreamWaitEvent(s2, e1, 0);

    // branch A: preps + layer-0 GEMM -> h0
    k_prep_a<<<1024, 256>>>(x, n, NF, 144, NF);
    k_prep_ball<<<264, 256>>>(W0, W1, W2, W3);
    k_wgemm<<<nCTA, 256, 77824>>>(ap, h0, 144, 152, B_OFF_L0);

    // branch B (s2): CSR build
    k_count<<<(e + 255) / 256, 256, 0, s2>>>(ei, e);
    k_scan1<<<nb, 1024, 0, s2>>>(n);
    k_scan2<<<1, 32, 0, s2>>>(nb);
    k_scan3<<<(n + 255) / 256, 256, 0, s2>>>(n);
    k_fill<<<(e + 255) / 256, 256, 0, s2>>>(ei, e);
    cudaEventRecord(e2, s2);
    cudaStreamWaitEvent(0, e2, 0);

    // layer 0 aggregate, then layers 1-3 (serial dependence)
    k_agg<<<agg_blocks, 256>>>((const __half*)h0, b0, out, n, 0);
    k_wgemm<<<nCTA, 256, 69632>>>(ap, h0, HD, 136, B_OFF_L1);
    k_agg<<<agg_blocks, 256>>>((const __half*)h0, b1, out, n, 0);
    k_wgemm<<<nCTA, 256, 69632>>>(ap, h0, HD, 136, B_OFF_L2);
    k_agg<<<agg_blocks, 256>>>((const __half*)h0, b2, out, n, 0);
    k_wgemm<<<nCTA, 256, 69632>>>(ap, h0, HD, 136, B_OFF_L3);
    k_agg<<<agg_blocks, 256>>>((const __half*)h0, b3, out, n, 1);
}